// round 1
// baseline (speedup 1.0000x reference)
#include <cuda_runtime.h>

#define B_   1024
#define T_   1024
#define HH   64
#define NBR  7          // batch rows per block
#define NTH  512
#define NBLK 147        // 147*7 = 1029 >= 1024

// ---- shared memory layout (float offsets, all 16B-aligned) ----
#define OFF_WIH    0            // 256*68 = 17408
#define OFF_WHH    17408        // 17408
#define OFF_WHEAD  34816        // 50*68 = 3400
#define OFF_WENCT  38216        // 23*64 = 1472
#define OFF_BG     39688        // 256
#define OFF_BENC   39944        // 64
#define OFF_BHEAD  40008        // 50 (+pad)
#define OFF_IN     40064        // 7*24 = 168 (+pad)
#define OFF_X      40240        // 7*64 = 448
#define OFF_H      40688        // 448
#define OFF_C      41136        // 448
#define OFF_GATE   41584        // 7*256 = 1792
#define SMEM_FLOATS 43376
#define SMEM_BYTES  (SMEM_FLOATS * 4)

// output offsets
#define OFFZ ((size_t)B_ * T_ * 18)                 // z starts here
#define OFFH ((size_t)B_ * T_ * 50)                 // hT
#define OFFC (OFFH + (size_t)B_ * HH)               // cT

__device__ __forceinline__ float sigm(float x) {
    return 1.0f / (1.0f + __expf(-x));
}

template <int CNT>
__device__ __forceinline__ void gate_core(const float* __restrict__ sWih,
                                          const float* __restrict__ sWhh,
                                          const float* __restrict__ sX,
                                          const float* __restrict__ sH,
                                          float* __restrict__ sGate,
                                          float bg, int g, int nb0) {
    float acc[CNT];
#pragma unroll
    for (int i = 0; i < CNT; i++) acc[i] = bg;
    const float4* wi = (const float4*)(sWih + g * 68);
    const float4* wh = (const float4*)(sWhh + g * 68);
#pragma unroll
    for (int k4 = 0; k4 < 16; k4++) {
        const float4 a = wi[k4];
        const float4 b = wh[k4];
#pragma unroll
        for (int i = 0; i < CNT; i++) {
            const float4 xv = *(const float4*)(sX + (nb0 + i) * 64 + k4 * 4);
            const float4 hv = *(const float4*)(sH + (nb0 + i) * 64 + k4 * 4);
            acc[i] = fmaf(a.x, xv.x, acc[i]);
            acc[i] = fmaf(a.y, xv.y, acc[i]);
            acc[i] = fmaf(a.z, xv.z, acc[i]);
            acc[i] = fmaf(a.w, xv.w, acc[i]);
            acc[i] = fmaf(b.x, hv.x, acc[i]);
            acc[i] = fmaf(b.y, hv.y, acc[i]);
            acc[i] = fmaf(b.z, hv.z, acc[i]);
            acc[i] = fmaf(b.w, hv.w, acc[i]);
        }
    }
#pragma unroll
    for (int i = 0; i < CNT; i++) sGate[(nb0 + i) * 256 + g] = acc[i];
}

__global__ __launch_bounds__(NTH, 1)
void wm_lstm_kernel(const float* __restrict__ obs, const float* __restrict__ act,
                    const float* __restrict__ h0,  const float* __restrict__ c0,
                    const float* __restrict__ Wenc, const float* __restrict__ benc,
                    const float* __restrict__ Wih,  const float* __restrict__ Whh,
                    const float* __restrict__ bih,  const float* __restrict__ bhh,
                    const float* __restrict__ Wpred, const float* __restrict__ bpred,
                    const float* __restrict__ Wz,    const float* __restrict__ bz,
                    float* __restrict__ out) {
    extern __shared__ float sm[];
    float* sWih   = sm + OFF_WIH;
    float* sWhh   = sm + OFF_WHH;
    float* sWhead = sm + OFF_WHEAD;
    float* sWencT = sm + OFF_WENCT;
    float* sBg    = sm + OFF_BG;
    float* sBenc  = sm + OFF_BENC;
    float* sBhead = sm + OFF_BHEAD;
    float* sIn    = sm + OFF_IN;
    float* sX     = sm + OFF_X;
    float* sH     = sm + OFF_H;
    float* sC     = sm + OFF_C;
    float* sGate  = sm + OFF_GATE;

    const int tid   = threadIdx.x;
    const int bBase = blockIdx.x * NBR;

    // ---- stage weights into shared (padded rows: stride 68) ----
    for (int idx = tid; idx < 256 * 64; idx += NTH) {
        int g = idx >> 6, k = idx & 63;
        sWih[g * 68 + k] = Wih[idx];
        sWhh[g * 68 + k] = Whh[idx];
    }
    for (int idx = tid; idx < 50 * 64; idx += NTH) {
        int o = idx >> 6, k = idx & 63;
        sWhead[o * 68 + k] = (o < 18) ? Wpred[o * 64 + k] : Wz[(o - 18) * 64 + k];
    }
    for (int idx = tid; idx < 23 * 64; idx += NTH) {
        int k = idx >> 6, j = idx & 63;
        sWencT[idx] = Wenc[j * 23 + k];   // transpose: [k][j]
    }
    if (tid < 256) sBg[tid] = bih[tid] + bhh[tid];
    if (tid < 64)  sBenc[tid] = benc[tid];
    if (tid < 50)  sBhead[tid] = (tid < 18) ? bpred[tid] : bz[tid - 18];
    if (tid < NBR * 64) {
        int nb = tid >> 6, j = tid & 63;
        int b = bBase + nb;
        float hv = 0.f, cv = 0.f;
        if (b < B_) { hv = h0[(size_t)b * HH + j]; cv = c0[(size_t)b * HH + j]; }
        sH[tid] = hv; sC[tid] = cv; sX[tid] = 0.f;
    }

    // ---- prefetch setup: 7*23 = 161 input scalars per step ----
    const int  pNb = tid / 23;
    const int  pK  = tid - pNb * 23;
    const int  pb  = bBase + pNb;
    const bool pValid = (tid < NBR * 23) && (pb < B_);
    const float* pPtr = nullptr;
    int pStep = 0;
    if (pValid) {
        if (pK < 18) { pPtr = obs + ((size_t)pb * T_) * 18 + pK;        pStep = 18; }
        else         { pPtr = act + ((size_t)pb * T_) * 5 + (pK - 18);  pStep = 5;  }
    }
    float rIn = pValid ? pPtr[0] : 0.f;   // t = 0

    // gate-phase constants
    const int gIdx = tid & 255;
    const bool hiHalf = (tid >= 256);

    // head-phase constants (350 = 7*50 head outputs)
    const bool headAct = (tid < NBR * 50);
    const int  hNb = tid / 50;
    const int  hO  = tid - hNb * 50;
    const int  hB  = bBase + hNb;
    const bool headW = headAct && (hB < B_);

    __syncthreads();

    for (int t = 0; t < T_; t++) {
        // A: commit prefetched inputs for this step
        if (tid < NBR * 23) sIn[pNb * 24 + pK] = rIn;
        __syncthreads();

        // B: encoder (448 x-values, one per thread) + prefetch t+1
        if (tid < NBR * 64) {
            int nb = tid >> 6, j = tid & 63;
            float a = sBenc[j];
#pragma unroll
            for (int k = 0; k < 23; k++)
                a = fmaf(sWencT[k * 64 + j], sIn[nb * 24 + k], a);
            sX[nb * 64 + j] = fmaxf(a, 0.f);
        }
        if (pValid && (t + 1 < T_)) rIn = __ldg(pPtr + (size_t)(t + 1) * pStep);
        __syncthreads();

        // C: gate GEMM (W_ih @ x + W_hh @ h + bias)
        if (!hiHalf) gate_core<4>(sWih, sWhh, sX, sH, sGate, sBg[gIdx], gIdx, 0);
        else         gate_core<3>(sWih, sWhh, sX, sH, sGate, sBg[gIdx], gIdx, 4);
        __syncthreads();

        // D: elementwise LSTM cell update (448 (nb,j) pairs)
        if (tid < NBR * 64) {
            int nb = tid >> 6, j = tid & 63;
            const float* gr = sGate + nb * 256;
            float gi = gr[j], gf = gr[64 + j], gg = gr[128 + j], go = gr[192 + j];
            float cc = sC[nb * 64 + j];
            cc = sigm(gf) * cc + sigm(gi) * tanhf(gg);
            float hh = sigm(go) * tanhf(cc);
            sC[nb * 64 + j] = cc;
            sH[nb * 64 + j] = hh;
        }
        __syncthreads();

        // E: output heads (pred_obs sigmoid + z), write global
        if (headAct) {
            float a = sBhead[hO];
            const float4* wr = (const float4*)(sWhead + hO * 68);
            const float4* hr = (const float4*)(sH + hNb * 64);
#pragma unroll
            for (int k4 = 0; k4 < 16; k4++) {
                const float4 w = wr[k4];
                const float4 h = hr[k4];
                a = fmaf(w.x, h.x, a);
                a = fmaf(w.y, h.y, a);
                a = fmaf(w.z, h.z, a);
                a = fmaf(w.w, h.w, a);
            }
            if (headW) {
                size_t row = (size_t)hB * T_ + t;
                if (hO < 18) out[row * 18 + hO] = sigm(a);
                else         out[OFFZ + row * 32 + (hO - 18)] = a;
            }
        }
        // loop-top __syncthreads orders head reads of sH vs next update
    }

    __syncthreads();
    // final hT / cT
    if (tid < NBR * 64) {
        int nb = tid >> 6, j = tid & 63;
        int b = bBase + nb;
        if (b < B_) {
            out[OFFH + (size_t)b * HH + j] = sH[nb * 64 + j];
            out[OFFC + (size_t)b * HH + j] = sC[nb * 64 + j];
        }
    }
}

extern "C" void kernel_launch(void* const* d_in, const int* in_sizes, int n_in,
                              void* d_out, int out_size) {
    (void)in_sizes; (void)n_in; (void)out_size;
    cudaFuncSetAttribute(wm_lstm_kernel,
                         cudaFuncAttributeMaxDynamicSharedMemorySize, SMEM_BYTES);
    wm_lstm_kernel<<<NBLK, NTH, SMEM_BYTES>>>(
        (const float*)d_in[0],  (const float*)d_in[1],
        (const float*)d_in[2],  (const float*)d_in[3],
        (const float*)d_in[4],  (const float*)d_in[5],
        (const float*)d_in[6],  (const float*)d_in[7],
        (const float*)d_in[8],  (const float*)d_in[9],
        (const float*)d_in[10], (const float*)d_in[11],
        (const float*)d_in[12], (const float*)d_in[13],
        (float*)d_out);
}

// round 6
// speedup vs baseline: 1.2653x; 1.2653x over previous
#include <cuda_runtime.h>

#define B_   1024
#define T_   1024
#define HH   64
#define NBR  7
#define NTH  512
#define NBLK 147        // 147*7 = 1029 >= 1024

// ---- shared memory layout (float offsets, 16B-aligned) ----
#define OFF_WHEAD 0         // 50*68 = 3400
#define OFF_WENCT 3400      // 23*64 = 1472 -> 4872
#define OFF_IN    4880      // 7*24 = 168   -> 5048
#define OFF_X     5056      // 448          -> 5504
#define OFF_H     5520      // gap 464 ≡ 16 mod 32 words -> sX/sH in disjoint banks
#define OFF_C     5968      // 448
#define OFF_GATE  6416      // 1792
#define SM_TOT    8208      // 32832 bytes

#define OFFZ ((size_t)B_ * T_ * 18)
#define OFFH ((size_t)B_ * T_ * 50)
#define OFFC (OFFH + (size_t)B_ * HH)

__device__ __forceinline__ float sigm(float x) {
    return 1.0f / (1.0f + __expf(-x));
}

__global__ __launch_bounds__(NTH, 1)
void wm_lstm_kernel(const float* __restrict__ obs, const float* __restrict__ act,
                    const float* __restrict__ h0,  const float* __restrict__ c0,
                    const float* __restrict__ Wenc, const float* __restrict__ benc,
                    const float* __restrict__ Wih,  const float* __restrict__ Whh,
                    const float* __restrict__ bih,  const float* __restrict__ bhh,
                    const float* __restrict__ Wpred, const float* __restrict__ bpred,
                    const float* __restrict__ Wz,    const float* __restrict__ bz,
                    float* __restrict__ out) {
    __shared__ float sm[SM_TOT];

    const int tid   = threadIdx.x;
    const int bBase = blockIdx.x * NBR;

    // ---- stage head/encoder weights into shared ----
    for (int idx = tid; idx < 50 * 64; idx += NTH) {
        int o = idx >> 6, k = idx & 63;
        sm[OFF_WHEAD + o * 68 + k] = (o < 18) ? Wpred[o * 64 + k] : Wz[(o - 18) * 64 + k];
    }
    for (int idx = tid; idx < 23 * 64; idx += NTH) {
        int k = idx >> 6, j = idx & 63;
        sm[OFF_WENCT + idx] = Wenc[j * 23 + k];   // transposed [k][j]
    }
    if (tid < NBR * 64) {
        int nb = tid >> 6, j = tid & 63;
        int b = bBase + nb;
        float hv = 0.f, cv = 0.f;
        if (b < B_) { hv = h0[(size_t)b * HH + j]; cv = c0[(size_t)b * HH + j]; }
        sm[OFF_H + tid] = hv; sm[OFF_C + tid] = cv; sm[OFF_X + tid] = 0.f;
    }

    // ---- gate setup: lane pair per gate, weights in REGISTERS ----
    const int  role = tid & 1;          // 0: W_ih (reads sX), 1: W_hh (reads sH)
    const int  g    = tid >> 1;         // gate 0..255
    float4 wreg[16];                    // this thread's 64 weight floats
    {
        const float* wsrc = (role ? Whh : Wih) + g * 64;
#pragma unroll
        for (int k4 = 0; k4 < 16; k4++)
            wreg[k4] = *(const float4*)(wsrc + k4 * 4);
    }
    const float* vbase = sm + (role ? OFF_H : OFF_X);
    const float  bg    = bih[g] + bhh[g];       // register, constant over t

    // ---- encoder constants ----
    const float be = (tid < NBR * 64) ? benc[tid & 63] : 0.f;

    // ---- input prefetch: 7*23 = 161 scalars per step ----
    const int  pNb = tid / 23;
    const int  pK  = tid - pNb * 23;
    const int  pb  = bBase + pNb;
    const bool pValid = (tid < NBR * 23) && (pb < B_);
    const float* pPtr = nullptr;
    int pStep = 0;
    if (pValid) {
        if (pK < 18) { pPtr = obs + ((size_t)pb * T_) * 18 + pK;       pStep = 18; }
        else         { pPtr = act + ((size_t)pb * T_) * 5 + (pK - 18); pStep = 5;  }
    }
    float rIn = pValid ? pPtr[0] : 0.f;

    // ---- head constants: ONE thread per head output (350 threads) ----
    const bool headAct = (tid < NBR * 50);
    const int  hNb = tid / 50;
    const int  hO  = tid - hNb * 50;
    const int  hB  = bBase + hNb;
    const bool headW = headAct && (hB < B_);
    const float bh = headAct ? ((hO < 18) ? bpred[hO] : bz[hO - 18]) : 0.f;

    __syncthreads();

    for (int t = 0; t < T_; t++) {
        // A: commit prefetched inputs
        if (tid < NBR * 23) sm[OFF_IN + pNb * 24 + pK] = rIn;
        __syncthreads();

        // B: encoder + prefetch next input
        if (tid < NBR * 64) {
            int nb = tid >> 6, j = tid & 63;
            float a = be;
#pragma unroll
            for (int k = 0; k < 23; k++)
                a = fmaf(sm[OFF_WENCT + k * 64 + j], sm[OFF_IN + nb * 24 + k], a);
            sm[OFF_X + nb * 64 + j] = fmaxf(a, 0.f);
        }
        if (pValid && (t + 1 < T_)) rIn = __ldg(pPtr + (size_t)(t + 1) * pStep);
        __syncthreads();

        // C: gate GEMM — scalar FFMA, register weights, pair-split
        {
            float acc[NBR];
#pragma unroll
            for (int i = 0; i < NBR; i++) acc[i] = 0.f;
#pragma unroll
            for (int k4 = 0; k4 < 16; k4++) {
                const float4 w = wreg[k4];
#pragma unroll
                for (int nb = 0; nb < NBR; nb++) {
                    const float4 v = *(const float4*)(vbase + nb * 64 + k4 * 4);
                    acc[nb] = fmaf(w.x, v.x, acc[nb]);
                    acc[nb] = fmaf(w.y, v.y, acc[nb]);
                    acc[nb] = fmaf(w.z, v.z, acc[nb]);
                    acc[nb] = fmaf(w.w, v.w, acc[nb]);
                }
            }
#pragma unroll
            for (int nb = 0; nb < NBR; nb++) {
                float s = acc[nb];
                s += __shfl_xor_sync(0xffffffffu, s, 1);
                if (!role) sm[OFF_GATE + nb * 256 + g] = s + bg;
            }
        }
        __syncthreads();

        // D: LSTM cell elementwise
        if (tid < NBR * 64) {
            int nb = tid >> 6, j = tid & 63;
            const float* gr = sm + OFF_GATE + nb * 256;
            float gi = gr[j], gf = gr[64 + j], gg = gr[128 + j], go = gr[192 + j];
            float cc = sm[OFF_C + nb * 64 + j];
            cc = sigm(gf) * cc + sigm(gi) * tanhf(gg);
            float hh = sigm(go) * tanhf(cc);
            sm[OFF_C + nb * 64 + j] = cc;
            sm[OFF_H + nb * 64 + j] = hh;
        }
        __syncthreads();

        // E: output heads — one thread per (nb, o) output
        if (headAct) {
            float a = bh;
            const float* wr = sm + OFF_WHEAD + hO * 68;
            const float* hr = sm + OFF_H + hNb * 64;
#pragma unroll
            for (int k4 = 0; k4 < 16; k4++) {
                const float4 w = *(const float4*)(wr + k4 * 4);
                const float4 h = *(const float4*)(hr + k4 * 4);
                a = fmaf(w.x, h.x, a);
                a = fmaf(w.y, h.y, a);
                a = fmaf(w.z, h.z, a);
                a = fmaf(w.w, h.w, a);
            }
            if (headW) {
                size_t row = (size_t)hB * T_ + t;
                if (hO < 18) out[row * 18 + hO] = sigm(a);
                else         out[OFFZ + row * 32 + (hO - 18)] = a;
            }
        }
        // loop-top sync (A) orders E's sH reads vs next D write
    }

    __syncthreads();
    if (tid < NBR * 64) {
        int nb = tid >> 6, j = tid & 63;
        int b = bBase + nb;
        if (b < B_) {
            out[OFFH + (size_t)b * HH + j] = sm[OFF_H + nb * 64 + j];
            out[OFFC + (size_t)b * HH + j] = sm[OFF_C + nb * 64 + j];
        }
    }
}

extern "C" void kernel_launch(void* const* d_in, const int* in_sizes, int n_in,
                              void* d_out, int out_size) {
    (void)in_sizes; (void)n_in; (void)out_size;
    wm_lstm_kernel<<<NBLK, NTH>>>(
        (const float*)d_in[0],  (const float*)d_in[1],
        (const float*)d_in[2],  (const float*)d_in[3],
        (const float*)d_in[4],  (const float*)d_in[5],
        (const float*)d_in[6],  (const float*)d_in[7],
        (const float*)d_in[8],  (const float*)d_in[9],
        (const float*)d_in[10], (const float*)d_in[11],
        (const float*)d_in[12], (const float*)d_in[13],
        (float*)d_out);
}